// round 11
// baseline (speedup 1.0000x reference)
#include <cuda_runtime.h>
#include <math.h>

#define NEMBD 768
#define LMAIN 1024
#define LSIDE 1024
#define BATCH 4
#define NHEAD 12
#define HDIM  64
#define HALF  (LSIDE/2)
#define ROWS  (BATCH*LMAIN)      // 4096
#define FFDIM 3072
#define LN_EPS 1e-5f

// ---------------- scratch (static device globals; no allocation) ----------------
__device__ float g_sn[ROWS*NEMBD];
__device__ float g_xn[ROWS*NEMBD];
__device__ float g_q [ROWS*NEMBD];
__device__ float g_k [ROWS*NEMBD];
__device__ float g_v [ROWS*NEMBD];
__device__ float g_y [ROWS*NEMBD];
__device__ float g_x1[ROWS*NEMBD];
__device__ float g_h0[ROWS*NEMBD];
__device__ float g_h [ROWS*FFDIM];
__device__ int   g_src [ROWS];
__device__ int   g_kmax[ROWS];

// ---------------- setup: gather indices + kmax, one block per batch ----------------
// thread 0: serial occurrence-count scan over mod_idx (mod_age pre-sorted =>
//           stable argsort is identity => scatter becomes running-count gather).
// threads 0..255: binary-search kmax for the 1024 queries of this batch
//           (kmax[b,q] = #{k : mod_age[b,k] <= age[b,q]}, both arrays sorted).
__global__ __launch_bounds__(256) void setup_kernel(const int* __restrict__ mod_idx,
                                                    const float* __restrict__ age,
                                                    const float* __restrict__ mod_age) {
    const int b = blockIdx.x, t = threadIdx.x;
    if (t == 0) {
        const int* mi = mod_idx + b * LSIDE;
        int base = b * HALF;
        int c2 = 0, c3 = 0;
        for (int j = 0; j < LSIDE; j++) {
            if (mi[j] == 2) g_src[b*LSIDE + j] = base + (c2++);
            else            g_src[b*LSIDE + j] = -(base + (c3++)) - 1;  // mod3 table
        }
    }
    const float* ma = mod_age + b * LSIDE;
    for (int qi = t; qi < LMAIN; qi += 256) {
        float a = age[b * LMAIN + qi];
        int lo = 0, hi = LSIDE;
        while (lo < hi) {
            int mid = (lo + hi) >> 1;
            if (ma[mid] <= a) lo = mid + 1; else hi = mid;
        }
        g_kmax[b * LMAIN + qi] = lo;
    }
}

// ---------------- LayerNorm over 768, one block per row, 256 threads ----------------
__device__ __forceinline__ void ln_row_body(const float* __restrict__ p,
                                            const float* __restrict__ w,
                                            const float* __restrict__ bb,
                                            float* __restrict__ o) {
    int t = threadIdx.x;
    float v0 = p[t], v1 = p[t + 256], v2 = p[t + 512];
    float s = v0 + v1 + v2;
    float q = v0*v0 + v1*v1 + v2*v2;
    #pragma unroll
    for (int off = 16; off; off >>= 1) {
        s += __shfl_xor_sync(0xffffffffu, s, off);
        q += __shfl_xor_sync(0xffffffffu, q, off);
    }
    __shared__ float ss[8], sq[8];
    int lane = t & 31, wid = t >> 5;
    if (lane == 0) { ss[wid] = s; sq[wid] = q; }
    __syncthreads();
    if (wid == 0) {
        float s2 = (lane < 8) ? ss[lane] : 0.f;
        float q2 = (lane < 8) ? sq[lane] : 0.f;
        #pragma unroll
        for (int off = 4; off; off >>= 1) {
            s2 += __shfl_xor_sync(0xffffffffu, s2, off);
            q2 += __shfl_xor_sync(0xffffffffu, q2, off);
        }
        if (lane == 0) { ss[0] = s2; sq[0] = q2; }
    }
    __syncthreads();
    float mean = ss[0] * (1.f / NEMBD);
    float var  = sq[0] * (1.f / NEMBD) - mean * mean;
    float rs = rsqrtf(var + LN_EPS);
    o[t]       = (v0 - mean) * rs * w[t]       + bb[t];
    o[t + 256] = (v1 - mean) * rs * w[t + 256] + bb[t + 256];
    o[t + 512] = (v2 - mean) * rs * w[t + 512] + bb[t + 512];
}

__global__ __launch_bounds__(256) void ln_kernel(const float* __restrict__ in,
                                                 const float* __restrict__ w,
                                                 const float* __restrict__ bb,
                                                 float* __restrict__ out) {
    int row = blockIdx.x;
    ln_row_body(in + (size_t)row * NEMBD, w, bb, out + (size_t)row * NEMBD);
}

__global__ __launch_bounds__(256) void gather_ln_kernel(const float* __restrict__ m2,
                                                        const float* __restrict__ m3,
                                                        const float* __restrict__ w,
                                                        const float* __restrict__ bb,
                                                        float* __restrict__ out) {
    int row = blockIdx.x;
    int src = g_src[row];
    const float* p = (src >= 0) ? (m2 + (size_t)src * NEMBD)
                                : (m3 + (size_t)(-src - 1) * NEMBD);
    ln_row_body(p, w, bb, out + (size_t)row * NEMBD);
}

// ---------------- GEMM core: C[M,N] = A[M,K] @ W[N,K]^T + bias, fused epilogue -----
// 128x128x16 tile, 8x8 per thread, register prefetch + 2-stage smem double buffer
// (single __syncthreads per k-step; WAR-safe: consecutive iterations use disjoint
//  smem buffers; barrier of step kt+1 orders compute(kt) before stores of kt+2).
// Vectorized float4 epilogue (8 contiguous n-columns per thread).
// MODE 0: +bias    MODE 1: +bias+residual    MODE 2: gelu(+bias)
template <int MODE>
__device__ __forceinline__ void gemm_body(const float* __restrict__ A,
                                          const float* __restrict__ W,
                                          const float* __restrict__ bias,
                                          const float* __restrict__ res,
                                          float* __restrict__ C,
                                          int M, int N, int K,
                                          int m0, int n0,
                                          float As[2][16][132],
                                          float Bs[2][16][132]) {
    const int tid = threadIdx.x;
    const int tx = tid & 15, ty = tid >> 4;

    float acc[8][8];
    #pragma unroll
    for (int i = 0; i < 8; i++)
        #pragma unroll
        for (int j = 0; j < 8; j++) acc[i][j] = 0.f;

    // per-thread load slots: 2 float4 of A, 2 of B per k-tile
    const int row0 = tid >> 2;            // slot 0: rows 0..63
    const int row1 = (tid + 256) >> 2;    // slot 1: rows 64..127
    const int c4   = tid & 3;
    const float* Ap0 = A + (size_t)(m0 + row0) * K + c4 * 4;
    const float* Ap1 = A + (size_t)(m0 + row1) * K + c4 * 4;
    const float* Bp0 = W + (size_t)(n0 + row0) * K + c4 * 4;
    const float* Bp1 = W + (size_t)(n0 + row1) * K + c4 * 4;

    float4 a0, a1, b0, b1;
    a0 = *(const float4*)(Ap0); a1 = *(const float4*)(Ap1);
    b0 = *(const float4*)(Bp0); b1 = *(const float4*)(Bp1);

    const int nsteps = K >> 4;
    int buf = 0;
    for (int kt = 0; kt < nsteps; kt++, buf ^= 1) {
        As[buf][c4*4+0][row0] = a0.x; As[buf][c4*4+1][row0] = a0.y;
        As[buf][c4*4+2][row0] = a0.z; As[buf][c4*4+3][row0] = a0.w;
        As[buf][c4*4+0][row1] = a1.x; As[buf][c4*4+1][row1] = a1.y;
        As[buf][c4*4+2][row1] = a1.z; As[buf][c4*4+3][row1] = a1.w;
        Bs[buf][c4*4+0][row0] = b0.x; Bs[buf][c4*4+1][row0] = b0.y;
        Bs[buf][c4*4+2][row0] = b0.z; Bs[buf][c4*4+3][row0] = b0.w;
        Bs[buf][c4*4+0][row1] = b1.x; Bs[buf][c4*4+1][row1] = b1.y;
        Bs[buf][c4*4+2][row1] = b1.z; Bs[buf][c4*4+3][row1] = b1.w;
        __syncthreads();

        if (kt + 1 < nsteps) {
            const int koff = (kt + 1) << 4;
            a0 = *(const float4*)(Ap0 + koff); a1 = *(const float4*)(Ap1 + koff);
            b0 = *(const float4*)(Bp0 + koff); b1 = *(const float4*)(Bp1 + koff);
        }

        #pragma unroll
        for (int kk = 0; kk < 16; kk++) {
            float af[8], bf[8];
            *(float4*)(af)     = *(const float4*)&As[buf][kk][ty * 8];
            *(float4*)(af + 4) = *(const float4*)&As[buf][kk][ty * 8 + 4];
            *(float4*)(bf)     = *(const float4*)&Bs[buf][kk][tx * 8];
            *(float4*)(bf + 4) = *(const float4*)&Bs[buf][kk][tx * 8 + 4];
            #pragma unroll
            for (int i = 0; i < 8; i++)
                #pragma unroll
                for (int j = 0; j < 8; j++) acc[i][j] = fmaf(af[i], bf[j], acc[i][j]);
        }
        // no trailing barrier: next iteration writes the other buffer
    }

    // vectorized epilogue: 8 contiguous n-columns per thread => 2 float4 per row
    const int nb = n0 + tx * 8;
    float bv[8];
    *(float4*)(bv)     = *(const float4*)(bias + nb);
    *(float4*)(bv + 4) = *(const float4*)(bias + nb + 4);
    #pragma unroll
    for (int i = 0; i < 8; i++) {
        const int m = m0 + ty * 8 + i;
        float v[8];
        #pragma unroll
        for (int j = 0; j < 8; j++) v[j] = acc[i][j] + bv[j];
        if (MODE == 1) {
            float rv[8];
            *(float4*)(rv)     = *(const float4*)(res + (size_t)m * N + nb);
            *(float4*)(rv + 4) = *(const float4*)(res + (size_t)m * N + nb + 4);
            #pragma unroll
            for (int j = 0; j < 8; j++) v[j] += rv[j];
        }
        if (MODE == 2) {
            #pragma unroll
            for (int j = 0; j < 8; j++)
                v[j] = 0.5f * v[j] * (1.0f + erff(v[j] * 0.70710678118654752f));
        }
        *(float4*)(C + (size_t)m * N + nb)     = *(const float4*)(v);
        *(float4*)(C + (size_t)m * N + nb + 4) = *(const float4*)(v + 4);
    }
}

template <int MODE>
__global__ __launch_bounds__(256) void gemm_kernel(const float* __restrict__ A,
                                                   const float* __restrict__ W,
                                                   const float* __restrict__ bias,
                                                   const float* __restrict__ res,
                                                   float* __restrict__ C,
                                                   int M, int N, int K) {
    __shared__ float As[2][16][132];
    __shared__ float Bs[2][16][132];
    gemm_body<MODE>(A, W, bias, res, C, M, N, K,
                    blockIdx.y * 128, blockIdx.x * 128, As, Bs);
}

// Batched QKV: blockIdx.z selects (A, W, bias, C). Q reads xn; K,V read sn.
// One launch => 576 CTAs instead of 3 x 192 => better chip fill.
__global__ __launch_bounds__(256) void gemm_qkv_kernel(const float* __restrict__ xn,
                                                       const float* __restrict__ sn,
                                                       const float* __restrict__ q_w,
                                                       const float* __restrict__ k_w,
                                                       const float* __restrict__ v_w,
                                                       const float* __restrict__ q_b,
                                                       const float* __restrict__ k_b,
                                                       const float* __restrict__ v_b,
                                                       float* __restrict__ q,
                                                       float* __restrict__ k,
                                                       float* __restrict__ v) {
    __shared__ float As[2][16][132];
    __shared__ float Bs[2][16][132];
    const int z = blockIdx.z;
    const float* A   = (z == 0) ? xn  : sn;
    const float* W   = (z == 0) ? q_w : (z == 1) ? k_w : v_w;
    const float* bia = (z == 0) ? q_b : (z == 1) ? k_b : v_b;
    float*       C   = (z == 0) ? q   : (z == 1) ? k   : v;
    gemm_body<0>(A, W, bia, nullptr, C, ROWS, NEMBD, NEMBD,
                 blockIdx.y * 128, blockIdx.x * 128, As, Bs);
}

// ---------------- flash attention with prefix mask ----------------
// grid (16 q-tiles, 12 heads, 4 batch), 256 threads (8 warps x 8 query rows)
__global__ __launch_bounds__(256) void attn_kernel() {
    extern __shared__ float sm[];
    float* Qs = sm;                    // [64][64]
    float* Ks = sm + 64 * 64;          // [64][65]  (padded vs bank conflicts)
    float* Vs = Ks + 64 * 65;          // [64][64]
    __shared__ int kms[64];

    const int b = blockIdx.z, h = blockIdx.y, q0 = blockIdx.x * 64;
    const int tid = threadIdx.x, lane = tid & 31, wid = tid >> 5;

    const float* qg = g_q + (size_t)(b * LMAIN + q0) * NEMBD + h * HDIM;
    for (int i = tid; i < 64 * 16; i += 256) {
        int r = i >> 4, c4 = i & 15;
        *(float4*)&Qs[r * 64 + c4 * 4] =
            *(const float4*)(qg + (size_t)r * NEMBD + c4 * 4);
    }
    if (tid < 64) kms[tid] = g_kmax[b * LMAIN + q0 + tid];
    __syncthreads();

    int kmx = 0;
    #pragma unroll 8
    for (int i = 0; i < 64; i++) kmx = max(kmx, kms[i]);
    const int nt = (kmx + 63) >> 6;

    const int rb = wid * 8;
    float mi[8], li[8], oo[8][2];
    int kr[8];
    int krw = 0;                                  // this warp's max key bound
    #pragma unroll
    for (int i = 0; i < 8; i++) {
        mi[i] = -1e30f; li[i] = 0.f; oo[i][0] = 0.f; oo[i][1] = 0.f;
        kr[i] = kms[rb + i];
        krw = max(krw, kr[i]);
    }

    const float* kg = g_k + (size_t)(b * LSIDE) * NEMBD + h * HDIM;
    const float* vg = g_v + (size_t)(b * LSIDE) * NEMBD + h * HDIM;

    for (int t = 0; t < nt; t++) {
        const int k0 = t * 64;
        __syncthreads();
        for (int i = tid; i < 64 * 16; i += 256) {
            int r = i >> 4, c4 = i & 15;
            float4 kv = *(const float4*)(kg + (size_t)(k0 + r) * NEMBD + c4 * 4);
            Ks[r * 65 + c4 * 4 + 0] = kv.x; Ks[r * 65 + c4 * 4 + 1] = kv.y;
            Ks[r * 65 + c4 * 4 + 2] = kv.z; Ks[r * 65 + c4 * 4 + 3] = kv.w;
            *(float4*)&Vs[r * 64 + c4 * 4] =
                *(const float4*)(vg + (size_t)(k0 + r) * NEMBD + c4 * 4);
        }
        __syncthreads();

        // warp-level early exit: every row this warp owns is fully masked
        // beyond krw (queries sorted by age => kmax non-decreasing). Predicate
        // is warp-uniform; only block-wide __syncthreads remain outside.
        if (k0 >= krw) continue;

        // scores: each lane owns keys (lane, lane+32) for this warp's 8 rows
        float s[8][2];
        #pragma unroll
        for (int i = 0; i < 8; i++) { s[i][0] = 0.f; s[i][1] = 0.f; }
        const float* kp0 = &Ks[lane * 65];
        const float* kp1 = &Ks[(lane + 32) * 65];
        #pragma unroll 16
        for (int d = 0; d < 64; d++) {
            float k0v = kp0[d], k1v = kp1[d];
            #pragma unroll
            for (int i = 0; i < 8; i++) {
                float qv = Qs[(rb + i) * 64 + d];   // warp-broadcast
                s[i][0] = fmaf(qv, k0v, s[i][0]);
                s[i][1] = fmaf(qv, k1v, s[i][1]);
            }
        }

        #pragma unroll
        for (int i = 0; i < 8; i++) {
            float s0 = s[i][0] * 0.125f, s1 = s[i][1] * 0.125f;
            int lim = kr[i];
            if (k0 + lane      >= lim) s0 = -1e30f;
            if (k0 + lane + 32 >= lim) s1 = -1e30f;
            float tm = fmaxf(s0, s1);
            #pragma unroll
            for (int off = 16; off; off >>= 1)
                tm = fmaxf(tm, __shfl_xor_sync(0xffffffffu, tm, off));
            float mnew = fmaxf(mi[i], tm);
            float p0 = __expf(s0 - mnew), p1 = __expf(s1 - mnew);
            float corr = __expf(mi[i] - mnew);
            mi[i] = mnew;
            float ps = p0 + p1;
            #pragma unroll
            for (int off = 16; off; off >>= 1)
                ps += __shfl_xor_sync(0xffffffffu, ps, off);
            li[i] = li[i] * corr + ps;
            float o0 = oo[i][0] * corr, o1 = oo[i][1] * corr;
            #pragma unroll
            for (int k = 0; k < 32; k++) {
                float pk = __shfl_sync(0xffffffffu, p0, k);
                float2 v2 = *(const float2*)&Vs[k * 64 + 2 * lane];
                o0 = fmaf(pk, v2.x, o0); o1 = fmaf(pk, v2.y, o1);
            }
            #pragma unroll
            for (int k = 0; k < 32; k++) {
                float pk = __shfl_sync(0xffffffffu, p1, k);
                float2 v2 = *(const float2*)&Vs[(k + 32) * 64 + 2 * lane];
                o0 = fmaf(pk, v2.x, o0); o1 = fmaf(pk, v2.y, o1);
            }
            oo[i][0] = o0; oo[i][1] = o1;
        }
    }

    float* yg = g_y + (size_t)(b * LMAIN + q0) * NEMBD + h * HDIM;
    #pragma unroll
    for (int i = 0; i < 8; i++) {
        int r = rb + i;
        float inv = (kr[i] > 0) ? (1.0f / li[i]) : 0.0f;  // all-masked rows => 0
        *(float2*)&yg[(size_t)r * NEMBD + 2 * lane] =
            make_float2(oo[i][0] * inv, oo[i][1] * inv);
    }
}

// ---------------- launch ----------------
extern "C" void kernel_launch(void* const* d_in, const int* in_sizes, int n_in,
                              void* d_out, int out_size) {
    const float* x       = (const float*)d_in[0];
    const float* age     = (const float*)d_in[1];
    const int*   mod_idx = (const int*)  d_in[2];
    const float* mod_age = (const float*)d_in[3];
    const float* m2      = (const float*)d_in[4];
    const float* m3      = (const float*)d_in[5];
    const float* ln0_w = (const float*)d_in[6],  *ln0_b = (const float*)d_in[7];
    const float* ln1_w = (const float*)d_in[8],  *ln1_b = (const float*)d_in[9];
    const float* ln2_w = (const float*)d_in[10], *ln2_b = (const float*)d_in[11];
    const float* q_w = (const float*)d_in[12], *q_b = (const float*)d_in[13];
    const float* k_w = (const float*)d_in[14], *k_b = (const float*)d_in[15];
    const float* v_w = (const float*)d_in[16], *v_b = (const float*)d_in[17];
    const float* c_w = (const float*)d_in[18], *c_b = (const float*)d_in[19];
    const float* fc_w = (const float*)d_in[20], *fc_b = (const float*)d_in[21];
    const float* pj_w = (const float*)d_in[22], *pj_b = (const float*)d_in[23];
    float* out = (float*)d_out;

    float *sn, *xn, *q, *k, *v, *y, *x1, *h0, *hh;
    cudaGetSymbolAddress((void**)&sn, g_sn);
    cudaGetSymbolAddress((void**)&xn, g_xn);
    cudaGetSymbolAddress((void**)&q,  g_q);
    cudaGetSymbolAddress((void**)&k,  g_k);
    cudaGetSymbolAddress((void**)&v,  g_v);
    cudaGetSymbolAddress((void**)&y,  g_y);
    cudaGetSymbolAddress((void**)&x1, g_x1);
    cudaGetSymbolAddress((void**)&h0, g_h0);
    cudaGetSymbolAddress((void**)&hh, g_h);

    // index prep + mask bounds (fused, one block per batch)
    setup_kernel<<<BATCH, 256>>>(mod_idx, age, mod_age);

    // norms
    gather_ln_kernel<<<ROWS, 256>>>(m2, m3, ln0_w, ln0_b, sn);   // sn = LN0(fused)
    ln_kernel<<<ROWS, 256>>>(x, ln1_w, ln1_b, xn);               // xn = LN1(x)

    // QKV projections: single batched launch (z = 0:Q, 1:K, 2:V)
    gemm_qkv_kernel<<<dim3(NEMBD/128, ROWS/128, 3), 256>>>(
        xn, sn, q_w, k_w, v_w, q_b, k_b, v_b, q, k, v);

    // attention
    cudaFuncSetAttribute(attn_kernel, cudaFuncAttributeMaxDynamicSharedMemorySize, 50176);
    attn_kernel<<<dim3(LMAIN/64, NHEAD, BATCH), 256, (64*64 + 64*65 + 64*64) * 4>>>();

    // x1 = x + y @ c_w^T + c_b
    gemm_kernel<1><<<dim3(NEMBD/128, ROWS/128), 256>>>(y, c_w, c_b, x, x1, ROWS, NEMBD, NEMBD);

    // MLP
    ln_kernel<<<ROWS, 256>>>(x1, ln2_w, ln2_b, h0);
    gemm_kernel<2><<<dim3(FFDIM/128, ROWS/128), 256>>>(h0, fc_w, fc_b, nullptr, hh, ROWS, FFDIM, NEMBD);
    gemm_kernel<1><<<dim3(NEMBD/128, ROWS/128), 256>>>(hh, pj_w, pj_b, x1, out, ROWS, NEMBD, FFDIM);
}

// round 13
// speedup vs baseline: 1.6009x; 1.6009x over previous
#include <cuda_runtime.h>
#include <cuda_bf16.h>
#include <math.h>
#include <stdint.h>

#define NEMBD 768
#define LMAIN 1024
#define LSIDE 1024
#define BATCH 4
#define NHEAD 12
#define HDIM  64
#define HALF  (LSIDE/2)
#define ROWS  (BATCH*LMAIN)      // 4096
#define FFDIM 3072
#define LN_EPS 1e-5f

// ---------------- scratch (static device globals; no allocation) ----------------
__device__ float g_sn[ROWS*NEMBD];
__device__ float g_xn[ROWS*NEMBD];
__device__ float g_q [ROWS*NEMBD];
__device__ float g_k [ROWS*NEMBD];
__device__ float g_v [ROWS*NEMBD];
__device__ float g_y [ROWS*NEMBD];
__device__ float g_x1[ROWS*NEMBD];
__device__ float g_h0[ROWS*NEMBD];
__device__ float g_h [ROWS*FFDIM];
__device__ int   g_src [ROWS];
__device__ int   g_kmax[ROWS];

// ---------------- helpers ----------------
__device__ __forceinline__ uint32_t smem_u32(const void* p) {
    uint32_t a;
    asm("{ .reg .u64 t; cvta.to.shared.u64 t, %1; cvt.u32.u64 %0, t; }" : "=r"(a) : "l"(p));
    return a;
}
__device__ __forceinline__ void ldsm4(uint32_t* r, uint32_t addr) {
    asm volatile("ldmatrix.sync.aligned.m8n8.x4.shared.b16 {%0,%1,%2,%3}, [%4];"
        : "=r"(r[0]), "=r"(r[1]), "=r"(r[2]), "=r"(r[3]) : "r"(addr));
}
__device__ __forceinline__ void mma_bf16(float* c, const uint32_t* a, const uint32_t* b) {
    asm volatile("mma.sync.aligned.m16n8k16.row.col.f32.bf16.bf16.f32 "
        "{%0,%1,%2,%3}, {%4,%5,%6,%7}, {%8,%9}, {%0,%1,%2,%3};"
        : "+f"(c[0]), "+f"(c[1]), "+f"(c[2]), "+f"(c[3])
        : "r"(a[0]), "r"(a[1]), "r"(a[2]), "r"(a[3]), "r"(b[0]), "r"(b[1]));
}

// ---------------- setup: gather indices + kmax, one block per batch ----------------
__global__ __launch_bounds__(256) void setup_kernel(const int* __restrict__ mod_idx,
                                                    const float* __restrict__ age,
                                                    const float* __restrict__ mod_age) {
    const int b = blockIdx.x, t = threadIdx.x;
    if (t == 0) {
        const int* mi = mod_idx + b * LSIDE;
        int base = b * HALF;
        int c2 = 0, c3 = 0;
        for (int j = 0; j < LSIDE; j++) {
            if (mi[j] == 2) g_src[b*LSIDE + j] = base + (c2++);
            else            g_src[b*LSIDE + j] = -(base + (c3++)) - 1;  // mod3 table
        }
    }
    const float* ma = mod_age + b * LSIDE;
    for (int qi = t; qi < LMAIN; qi += 256) {
        float a = age[b * LMAIN + qi];
        int lo = 0, hi = LSIDE;
        while (lo < hi) {
            int mid = (lo + hi) >> 1;
            if (ma[mid] <= a) lo = mid + 1; else hi = mid;
        }
        g_kmax[b * LMAIN + qi] = lo;
    }
}

// ---------------- LayerNorm over 768, one block per row, 256 threads ----------------
__device__ __forceinline__ void ln_row_body(const float* __restrict__ p,
                                            const float* __restrict__ w,
                                            const float* __restrict__ bb,
                                            float* __restrict__ o) {
    int t = threadIdx.x;
    float v0 = p[t], v1 = p[t + 256], v2 = p[t + 512];
    float s = v0 + v1 + v2;
    float q = v0*v0 + v1*v1 + v2*v2;
    #pragma unroll
    for (int off = 16; off; off >>= 1) {
        s += __shfl_xor_sync(0xffffffffu, s, off);
        q += __shfl_xor_sync(0xffffffffu, q, off);
    }
    __shared__ float ss[8], sq[8];
    int lane = t & 31, wid = t >> 5;
    if (lane == 0) { ss[wid] = s; sq[wid] = q; }
    __syncthreads();
    if (wid == 0) {
        float s2 = (lane < 8) ? ss[lane] : 0.f;
        float q2 = (lane < 8) ? sq[lane] : 0.f;
        #pragma unroll
        for (int off = 4; off; off >>= 1) {
            s2 += __shfl_xor_sync(0xffffffffu, s2, off);
            q2 += __shfl_xor_sync(0xffffffffu, q2, off);
        }
        if (lane == 0) { ss[0] = s2; sq[0] = q2; }
    }
    __syncthreads();
    float mean = ss[0] * (1.f / NEMBD);
    float var  = sq[0] * (1.f / NEMBD) - mean * mean;
    float rs = rsqrtf(var + LN_EPS);
    o[t]       = (v0 - mean) * rs * w[t]       + bb[t];
    o[t + 256] = (v1 - mean) * rs * w[t + 256] + bb[t + 256];
    o[t + 512] = (v2 - mean) * rs * w[t + 512] + bb[t + 512];
}

__global__ __launch_bounds__(256) void ln_kernel(const float* __restrict__ in,
                                                 const float* __restrict__ w,
                                                 const float* __restrict__ bb,
                                                 float* __restrict__ out) {
    int row = blockIdx.x;
    ln_row_body(in + (size_t)row * NEMBD, w, bb, out + (size_t)row * NEMBD);
}

__global__ __launch_bounds__(256) void gather_ln_kernel(const float* __restrict__ m2,
                                                        const float* __restrict__ m3,
                                                        const float* __restrict__ w,
                                                        const float* __restrict__ bb,
                                                        float* __restrict__ out) {
    int row = blockIdx.x;
    int src = g_src[row];
    const float* p = (src >= 0) ? (m2 + (size_t)src * NEMBD)
                                : (m3 + (size_t)(-src - 1) * NEMBD);
    ln_row_body(p, w, bb, out + (size_t)row * NEMBD);
}

// ---------------- warp-MMA GEMM: C[M,N] = A[M,K] @ W[N,K]^T + bias ----------------
// bf16 hi/lo split: x = hi + lo; D = Ah*Bh + Ah*Bl + Al*Bh (lo*lo ~2^-16 rel, dropped).
// mma.sync m16n8k16 (generic PTX, works under compute_103 — tcgen05 does NOT).
// Tile 128x128, 8 warps as 2(m) x 4(n), warp-tile 64x32, K-chunk 32 fp32 per stage.
// smem: bf16 tiles Ah/Al/Bh/Bl, 128 rows x 32 cols, ldm=40 bf16 (80B rows: ldmatrix
// row addresses land in distinct 128B groups => conflict-free; 16B aligned).
// MODE 0: +bias   MODE 1: +bias+residual   MODE 2: gelu(+bias)
#define LDM 40

__device__ __forceinline__ void cvt_pair8(char* hi, char* lo, uint32_t off, float4 v) {
    __nv_bfloat16 h0 = __float2bfloat16(v.x), h1 = __float2bfloat16(v.y);
    __nv_bfloat16 h2 = __float2bfloat16(v.z), h3 = __float2bfloat16(v.w);
    float l0 = v.x - __bfloat162float(h0), l1 = v.y - __bfloat162float(h1);
    float l2 = v.z - __bfloat162float(h2), l3 = v.w - __bfloat162float(h3);
    uint32_t hA = (uint32_t)__bfloat16_as_ushort(h0) | ((uint32_t)__bfloat16_as_ushort(h1) << 16);
    uint32_t hB = (uint32_t)__bfloat16_as_ushort(h2) | ((uint32_t)__bfloat16_as_ushort(h3) << 16);
    __nv_bfloat16 g0 = __float2bfloat16(l0), g1 = __float2bfloat16(l1);
    __nv_bfloat16 g2 = __float2bfloat16(l2), g3 = __float2bfloat16(l3);
    uint32_t lA = (uint32_t)__bfloat16_as_ushort(g0) | ((uint32_t)__bfloat16_as_ushort(g1) << 16);
    uint32_t lB = (uint32_t)__bfloat16_as_ushort(g2) | ((uint32_t)__bfloat16_as_ushort(g3) << 16);
    *(uint2*)(hi + off) = make_uint2(hA, hB);
    *(uint2*)(lo + off) = make_uint2(lA, lB);
}

template <int MODE>
__device__ void wm_gemm_body(const float* __restrict__ A, const float* __restrict__ W,
                             const float* __restrict__ bias, const float* __restrict__ res,
                             float* __restrict__ C, int N, int K, int m0, int n0) {
    __shared__ __align__(16) __nv_bfloat16 Ah[128*LDM], Al[128*LDM], Bh[128*LDM], Bl[128*LDM];
    const int tid = threadIdx.x, wid = tid >> 5, lane = tid & 31;
    const int warp_m = wid >> 2, warp_n = wid & 3;       // 2 x 4 warp grid

    const uint32_t ahb = smem_u32(Ah), alb = smem_u32(Al);
    const uint32_t bhb = smem_u32(Bh), blb = smem_u32(Bl);

    float acc[4][4][4];
    #pragma unroll
    for (int i = 0; i < 4; i++)
        #pragma unroll
        for (int j = 0; j < 4; j++)
            #pragma unroll
            for (int r = 0; r < 4; r++) acc[i][j][r] = 0.f;

    // staging map: 256 threads cover 128 rows x 8 float4-cols in 4 passes
    const int srow = tid >> 3, sf4 = tid & 7;

    // ldmatrix addresses (element offsets; bytes = *2)
    // A tile tm, k16: row = warp_m*64 + tm*16 + lane%16 ; koff = k16*16 + (lane/16)*8
    const int a_row = warp_m * 64 + (lane & 15);
    const int a_koff = (lane >> 4) * 8;
    // B group g (two n8 tiles), k16: n = warp_n*32 + g*16 + (lane/16)*8 + lane%8 ; koff = k16*16 + ((lane/8)&1)*8
    const int b_nrow = warp_n * 32 + (lane >> 4) * 8 + (lane & 7);
    const int b_koff = ((lane >> 3) & 1) * 8;

    const int nkt = K >> 5;
    for (int kt = 0; kt < nkt; kt++) {
        const int k0 = kt << 5;
        #pragma unroll
        for (int p = 0; p < 4; p++) {
            const int row = p * 32 + srow;
            float4 av = *(const float4*)(A + (size_t)(m0 + row) * K + k0 + sf4 * 4);
            float4 bv = *(const float4*)(W + (size_t)(n0 + row) * K + k0 + sf4 * 4);
            const uint32_t off = (uint32_t)(row * (LDM*2) + sf4 * 8);
            cvt_pair8((char*)Ah, (char*)Al, off, av);
            cvt_pair8((char*)Bh, (char*)Bl, off, bv);
        }
        __syncthreads();

        #pragma unroll
        for (int k16 = 0; k16 < 2; k16++) {
            uint32_t ah[4][4], al[4][4], bh[4][2], bl[4][2];
            #pragma unroll
            for (int tm = 0; tm < 4; tm++) {
                const uint32_t aoff = (uint32_t)((a_row + tm * 16) * (LDM*2) + (k16 * 16 + a_koff) * 2);
                ldsm4(ah[tm], ahb + aoff);
                ldsm4(al[tm], alb + aoff);
            }
            #pragma unroll
            for (int g = 0; g < 2; g++) {
                const uint32_t boff = (uint32_t)((b_nrow + g * 16) * (LDM*2) + (k16 * 16 + b_koff) * 2);
                uint32_t th[4], tl[4];
                ldsm4(th, bhb + boff);
                ldsm4(tl, blb + boff);
                bh[g*2+0][0] = th[0]; bh[g*2+0][1] = th[1];
                bh[g*2+1][0] = th[2]; bh[g*2+1][1] = th[3];
                bl[g*2+0][0] = tl[0]; bl[g*2+0][1] = tl[1];
                bl[g*2+1][0] = tl[2]; bl[g*2+1][1] = tl[3];
            }
            #pragma unroll
            for (int tm = 0; tm < 4; tm++)
                #pragma unroll
                for (int tn = 0; tn < 4; tn++) {
                    mma_bf16(acc[tm][tn], ah[tm], bh[tn]);
                    mma_bf16(acc[tm][tn], ah[tm], bl[tn]);
                    mma_bf16(acc[tm][tn], al[tm], bh[tn]);
                }
        }
        __syncthreads();
    }

    // epilogue: c0,c1 -> row g; c2,c3 -> row g+8; cols (lane%4)*2, +1
    const int er = lane >> 2, ec = (lane & 3) * 2;
    #pragma unroll
    for (int tm = 0; tm < 4; tm++) {
        #pragma unroll
        for (int tn = 0; tn < 4; tn++) {
            const int gn = n0 + warp_n * 32 + tn * 8 + ec;
            float2 bv = *(const float2*)(bias + gn);
            #pragma unroll
            for (int h = 0; h < 2; h++) {
                const int gm = m0 + warp_m * 64 + tm * 16 + er + h * 8;
                float2 v = make_float2(acc[tm][tn][h*2+0] + bv.x,
                                       acc[tm][tn][h*2+1] + bv.y);
                if (MODE == 1) {
                    float2 rv = *(const float2*)(res + (size_t)gm * N + gn);
                    v.x += rv.x; v.y += rv.y;
                }
                if (MODE == 2) {
                    v.x = 0.5f * v.x * (1.0f + erff(v.x * 0.70710678118654752f));
                    v.y = 0.5f * v.y * (1.0f + erff(v.y * 0.70710678118654752f));
                }
                *(float2*)(C + (size_t)gm * N + gn) = v;
            }
        }
    }
}

template <int MODE>
__global__ __launch_bounds__(256) void wm_gemm_kernel(const float* __restrict__ A,
                                                      const float* __restrict__ W,
                                                      const float* __restrict__ bias,
                                                      const float* __restrict__ res,
                                                      float* __restrict__ C,
                                                      int N, int K) {
    wm_gemm_body<MODE>(A, W, bias, res, C, N, K, blockIdx.y * 128, blockIdx.x * 128);
}

__global__ __launch_bounds__(256) void wm_gemm_qkv(const float* __restrict__ xn,
                                                   const float* __restrict__ sn,
                                                   const float* __restrict__ q_w,
                                                   const float* __restrict__ k_w,
                                                   const float* __restrict__ v_w,
                                                   const float* __restrict__ q_b,
                                                   const float* __restrict__ k_b,
                                                   const float* __restrict__ v_b,
                                                   float* __restrict__ q,
                                                   float* __restrict__ k,
                                                   float* __restrict__ v) {
    const int z = blockIdx.z;
    const float* A   = (z == 0) ? xn  : sn;
    const float* W   = (z == 0) ? q_w : (z == 1) ? k_w : v_w;
    const float* bia = (z == 0) ? q_b : (z == 1) ? k_b : v_b;
    float*       C   = (z == 0) ? q   : (z == 1) ? k   : v;
    wm_gemm_body<0>(A, W, bia, nullptr, C, NEMBD, NEMBD, blockIdx.y * 128, blockIdx.x * 128);
}

// ---------------- flash attention with prefix mask (unchanged, passing) ----------------
__global__ __launch_bounds__(256) void attn_kernel() {
    extern __shared__ float sm[];
    float* Qs = sm;                    // [64][64]
    float* Ks = sm + 64 * 64;          // [64][65]
    float* Vs = Ks + 64 * 65;          // [64][64]
    __shared__ int kms[64];

    const int b = blockIdx.z, h = blockIdx.y, q0 = blockIdx.x * 64;
    const int tid = threadIdx.x, lane = tid & 31, wid = tid >> 5;

    const float* qg = g_q + (size_t)(b * LMAIN + q0) * NEMBD + h * HDIM;
    for (int i = tid; i < 64 * 16; i += 256) {
        int r = i >> 4, c4 = i & 15;
        *(float4*)&Qs[r * 64 + c4 * 4] =
            *(const float4*)(qg + (size_t)r * NEMBD + c4 * 4);
    }
    if (tid < 64) kms[tid] = g_kmax[b * LMAIN + q0 + tid];
    __syncthreads();

    int kmx = 0;
    #pragma unroll 8
    for (int i = 0; i < 64; i++) kmx = max(kmx, kms[i]);
    const int nt = (kmx + 63) >> 6;

    const int rb = wid * 8;
    float mi[8], li[8], oo[8][2];
    int kr[8];
    int krw = 0;
    #pragma unroll
    for (int i = 0; i < 8; i++) {
        mi[i] = -1e30f; li[i] = 0.f; oo[i][0] = 0.f; oo[i][1] = 0.f;
        kr[i] = kms[rb + i];
        krw = max(krw, kr[i]);
    }

    const float* kg = g_k + (size_t)(b * LSIDE) * NEMBD + h * HDIM;
    const float* vg = g_v + (size_t)(b * LSIDE) * NEMBD + h * HDIM;

    for (int t = 0; t < nt; t++) {
        const int k0 = t * 64;
        __syncthreads();
        for (int i = tid; i < 64 * 16; i += 256) {
            int r = i >> 4, c4 = i & 15;
            float4 kv = *(const float4*)(kg + (size_t)(k0 + r) * NEMBD + c4 * 4);
            Ks[r * 65 + c4 * 4 + 0] = kv.x; Ks[r * 65 + c4 * 4 + 1] = kv.y;
            Ks[r * 65 + c4 * 4 + 2] = kv.z; Ks[r * 65 + c4 * 4 + 3] = kv.w;
            *(float4*)&Vs[r * 64 + c4 * 4] =
                *(const float4*)(vg + (size_t)(k0 + r) * NEMBD + c4 * 4);
        }
        __syncthreads();

        if (k0 >= krw) continue;   // warp-uniform early exit (kmax sorted)

        float s[8][2];
        #pragma unroll
        for (int i = 0; i < 8; i++) { s[i][0] = 0.f; s[i][1] = 0.f; }
        const float* kp0 = &Ks[lane * 65];
        const float* kp1 = &Ks[(lane + 32) * 65];
        #pragma unroll 16
        for (int d = 0; d < 64; d++) {
            float k0v = kp0[d], k1v = kp1[d];
            #pragma unroll
            for (int i = 0; i < 8; i++) {
                float qv = Qs[(rb + i) * 64 + d];
                s[i][0] = fmaf(qv, k0v, s[i][0]);
                s[i][1] = fmaf(qv, k1v, s[i][1]);
            }
        }

        #pragma unroll
        for (int i = 0; i < 8; i++) {
            float s0 = s[i][0] * 0.125f, s1 = s[i][1] * 0.125f;
            int lim = kr[i];
            if (k0 + lane      >= lim) s0 = -1e30f;
            if (k0 + lane + 32 >= lim) s1 = -1e30f;
            float tm = fmaxf(s0, s1);
            #pragma unroll
            for (int off = 16; off; off >>= 1)
                tm = fmaxf(tm, __shfl_xor_sync(0xffffffffu, tm, off));
            float mnew = fmaxf(mi[i], tm);
            float p0 = __expf(s0 - mnew), p1 = __expf(s1 - mnew);
            float corr = __expf(mi[i] - mnew);
            mi[i] = mnew;
            float ps = p0 + p1;
            #pragma unroll
            for (int off = 16; off; off >>= 1)
                ps += __shfl_xor_sync(0xffffffffu, ps, off);
            li[i] = li[i] * corr + ps;
            float o0 = oo[i][0] * corr, o1 = oo[i][1] * corr;
            #pragma unroll
            for (int k = 0; k < 32; k++) {
                float pk = __shfl_sync(0xffffffffu, p0, k);
                float2 v2 = *(const float2*)&Vs[k * 64 + 2 * lane];
                o0 = fmaf(pk, v2.x, o0); o1 = fmaf(pk, v2.y, o1);
            }
            #pragma unroll
            for (int k = 0; k < 32; k++) {
                float pk = __shfl_sync(0xffffffffu, p1, k);
                float2 v2 = *(const float2*)&Vs[(k + 32) * 64 + 2 * lane];
                o0 = fmaf(pk, v2.x, o0); o1 = fmaf(pk, v2.y, o1);
            }
            oo[i][0] = o0; oo[i][1] = o1;
        }
    }

    float* yg = g_y + (size_t)(b * LMAIN + q0) * NEMBD + h * HDIM;
    #pragma unroll
    for (int i = 0; i < 8; i++) {
        int r = rb + i;
        float inv = (kr[i] > 0) ? (1.0f / li[i]) : 0.0f;
        *(float2*)&yg[(size_t)r * NEMBD + 2 * lane] =
            make_float2(oo[i][0] * inv, oo[i][1] * inv);
    }
}

// ---------------- launch ----------------
extern "C" void kernel_launch(void* const* d_in, const int* in_sizes, int n_in,
                              void* d_out, int out_size) {
    const float* x       = (const float*)d_in[0];
    const float* age     = (const float*)d_in[1];
    const int*   mod_idx = (const int*)  d_in[2];
    const float* mod_age = (const float*)d_in[3];
    const float* m2      = (const float*)d_in[4];
    const float* m3      = (const float*)d_in[5];
    const float* ln0_w = (const float*)d_in[6],  *ln0_b = (const float*)d_in[7];
    const float* ln1_w = (const float*)d_in[8],  *ln1_b = (const float*)d_in[9];
    const float* ln2_w = (const float*)d_in[10], *ln2_b = (const float*)d_in[11];
    const float* q_w = (const float*)d_in[12], *q_b = (const float*)d_in[13];
    const float* k_w = (const float*)d_in[14], *k_b = (const float*)d_in[15];
    const float* v_w = (const float*)d_in[16], *v_b = (const float*)d_in[17];
    const float* c_w = (const float*)d_in[18], *c_b = (const float*)d_in[19];
    const float* fc_w = (const float*)d_in[20], *fc_b = (const float*)d_in[21];
    const float* pj_w = (const float*)d_in[22], *pj_b = (const float*)d_in[23];
    float* out = (float*)d_out;

    float *sn, *xn, *q, *k, *v, *y, *x1, *h0, *hh;
    cudaGetSymbolAddress((void**)&sn, g_sn);
    cudaGetSymbolAddress((void**)&xn, g_xn);
    cudaGetSymbolAddress((void**)&q,  g_q);
    cudaGetSymbolAddress((void**)&k,  g_k);
    cudaGetSymbolAddress((void**)&v,  g_v);
    cudaGetSymbolAddress((void**)&y,  g_y);
    cudaGetSymbolAddress((void**)&x1, g_x1);
    cudaGetSymbolAddress((void**)&h0, g_h0);
    cudaGetSymbolAddress((void**)&hh, g_h);

    cudaFuncSetAttribute(attn_kernel, cudaFuncAttributeMaxDynamicSharedMemorySize, 50176);

    // index prep + mask bounds (fused, one block per batch)
    setup_kernel<<<BATCH, 256>>>(mod_idx, age, mod_age);

    // norms
    gather_ln_kernel<<<ROWS, 256>>>(m2, m3, ln0_w, ln0_b, sn);   // sn = LN0(fused)
    ln_kernel<<<ROWS, 256>>>(x, ln1_w, ln1_b, xn);               // xn = LN1(x)

    // QKV projections: single batched warp-MMA launch (z = 0:Q, 1:K, 2:V)
    wm_gemm_qkv<<<dim3(NEMBD/128, ROWS/128, 3), 256>>>(
        xn, sn, q_w, k_w, v_w, q_b, k_b, v_b, q, k, v);

    // attention
    attn_kernel<<<dim3(LMAIN/64, NHEAD, BATCH), 256, (64*64 + 64*65 + 64*64) * 4>>>();

    // x1 = x + y @ c_w^T + c_b
    wm_gemm_kernel<1><<<dim3(NEMBD/128, ROWS/128), 256>>>(y, c_w, c_b, x, x1, NEMBD, NEMBD);

    // MLP
    ln_kernel<<<ROWS, 256>>>(x1, ln2_w, ln2_b, h0);
    wm_gemm_kernel<2><<<dim3(FFDIM/128, ROWS/128), 256>>>(h0, fc_w, fc_b, nullptr, hh, FFDIM, NEMBD);
    wm_gemm_kernel<1><<<dim3(NEMBD/128, ROWS/128), 256>>>(hh, pj_w, pj_b, x1, out, NEMBD, FFDIM);
}